// round 12
// baseline (speedup 1.0000x reference)
#include <cuda_runtime.h>
#include <cuda_pipeline.h>

#define BB 4
#define CC 64
#define HH 128
#define WW 416
#define HW (HH*WW)
#define CHW (CC*HH*WW)

// Scratch for warped x2 (no cudaMalloc allowed)
__device__ float g_x2w[(size_t)BB*CHW];

__device__ __forceinline__ float lrelu(float v) { return v >= 0.f ? v : 0.1f*v; }

// ===========================================================================
// Fused kernel: blocks 0..3 in x = 192-ch disparity cost volume (FMA-bound)
//               blocks 4..7 in x = bilinear warp of x2 (latency-bound filler)
// 16d x 4x per thread; __launch_bounds__(320,2) -> 2 resident blocks/SM.
// (unchanged from R11 champion)
// ===========================================================================
#define TXD 104
#define RWD 296                         // 104 + 191 halo, padded to mult of 4
#define CTD 16
#define NTD (CC/CTD)                    // 4 pipeline stages
#define DISP_BUF (CTD*TXD + CTD*RWD)    // 6400 floats per buffer
#define DSP_SMEM (2*DISP_BUF*4)         // 51200 B

__global__ __launch_bounds__(320, 2)
void fused_disp_warp(const float* __restrict__ x1, const float* __restrict__ r1,
                     const float* __restrict__ x2, const float* __restrict__ flow,
                     float* __restrict__ out) {
    extern __shared__ float sm[];
    const int y = blockIdx.y, b = blockIdx.z;
    const int t = threadIdx.x;

    if (blockIdx.x >= 4) {
        // ------------------ warp path ------------------
        const int x0t = (blockIdx.x - 4) * TXD;
        float* s_w = sm;                  // [4][TXD] weights
        int*   s_i = (int*)(sm + 4*TXD);  // [4][TXD] gather indices

        if (t < TXD) {
            const int x = x0t + t;
            const float fx = flow[((size_t)(b*2+0)*HH + y)*WW + x];
            const float fy = flow[((size_t)(b*2+1)*HH + y)*WW + x];
            const float gx = (float)x + fx;
            const float gy = (float)y + fy;
            const float x0f = floorf(gx), y0f = floorf(gy);
            const float wx = gx - x0f, wy = gy - y0f;
            const int x0 = (int)x0f, y0 = (int)y0f;
            const int x1i = x0 + 1,  y1i = y0 + 1;

            const float vx0 = (x0  >= 0 && x0  < WW) ? 1.f : 0.f;
            const float vx1 = (x1i >= 0 && x1i < WW) ? 1.f : 0.f;
            const float vy0 = (y0  >= 0 && y0  < HH) ? 1.f : 0.f;
            const float vy1 = (y1i >= 0 && y1i < HH) ? 1.f : 0.f;

            const int x0c = min(max(x0, 0), WW-1);
            const int x1c = min(max(x1i,0), WW-1);
            const int y0c = min(max(y0, 0), HH-1);
            const int y1c = min(max(y1i,0), HH-1);

            s_w[0*TXD+t] = (1.f-wx)*(1.f-wy)*vx0*vy0;
            s_w[1*TXD+t] = wx*(1.f-wy)*vx1*vy0;
            s_w[2*TXD+t] = (1.f-wx)*wy*vx0*vy1;
            s_w[3*TXD+t] = wx*wy*vx1*vy1;
            s_i[0*TXD+t] = y0c*WW + x0c;
            s_i[1*TXD+t] = y0c*WW + x1c;
            s_i[2*TXD+t] = y1c*WW + x0c;
            s_i[3*TXD+t] = y1c*WW + x1c;
        }
        __syncthreads();

        const float* xb = x2 + (size_t)b*CHW;
        float* ob = g_x2w + (size_t)b*CHW + (size_t)y*WW + x0t;
        for (int e = t; e < TXD*CC; e += 320) {
            const int c = e / TXD, xi = e - c*TXD;
            const float w00 = s_w[0*TXD+xi], w01 = s_w[1*TXD+xi];
            const float w10 = s_w[2*TXD+xi], w11 = s_w[3*TXD+xi];
            const int i00 = s_i[0*TXD+xi], i01 = s_i[1*TXD+xi];
            const int i10 = s_i[2*TXD+xi], i11 = s_i[3*TXD+xi];
            const float* p = xb + (size_t)c*HW;
            ob[(size_t)c*HW + xi] = w00*__ldg(p+i00) + w01*__ldg(p+i01)
                                  + w10*__ldg(p+i10) + w11*__ldg(p+i11);
        }
        return;
    }

    // ------------------ disparity path ------------------
    const int x0t = blockIdx.x * TXD;
    const int dg = t / 26;
    const int xg = t - dg*26;
    const bool act = (t < 312);

    const float* x1p = x1 + (size_t)b*CHW + (size_t)y*WW + x0t;
    const float* rp  = r1 + (size_t)b*CHW + (size_t)y*WW;

    float acc[16][4];
#pragma unroll
    for (int i = 0; i < 16; i++)
#pragma unroll
        for (int j = 0; j < 4; j++) acc[i][j] = 0.f;

    auto load_tile = [&](int bi, int kt) {
        float* da = sm + bi*DISP_BUF;
        float* dr = da + CTD*TXD;
        const int ct = kt * CTD;
#pragma unroll
        for (int i = t; i < CTD*26; i += 320) {
            int c = i / 26, x4 = (i - 26*c) * 4;
            __pipeline_memcpy_async(da + c*TXD + x4,
                                    x1p + (size_t)(ct+c)*HW + x4, 16);
        }
#pragma unroll
        for (int i = t; i < CTD*74; i += 320) {
            int c = i / 74, x4 = (i - 74*c) * 4;
            int gx = x0t - 96 + x4;
            float* dst = dr + c*RWD + x4;
            if ((unsigned)gx < WW)
                __pipeline_memcpy_async(dst, rp + (size_t)(ct+c)*HW + gx, 16);
            else
                *reinterpret_cast<float4*>(dst) = make_float4(0.f,0.f,0.f,0.f);
        }
    };

    load_tile(0, 0);
    __pipeline_commit();

    for (int k = 0; k < NTD; k++) {
        if (k + 1 < NTD) {
            load_tile((k+1) & 1, k+1);
            __pipeline_commit();
            __pipeline_wait_prior(1);
        } else {
            __pipeline_wait_prior(0);
        }
        __syncthreads();

        if (act) {
            const float* da = sm + (k&1)*DISP_BUF;
            const float* ap = da + xg*4;
            const float* bp = da + CTD*TXD + xg*4 + dg*16;
#pragma unroll 4
            for (int c = 0; c < CTD; c++) {
                const float4 a  = *reinterpret_cast<const float4*>(ap + c*TXD);
                const float4 q0 = *reinterpret_cast<const float4*>(bp + c*RWD);
                const float4 q1 = *reinterpret_cast<const float4*>(bp + c*RWD + 4);
                const float4 q2 = *reinterpret_cast<const float4*>(bp + c*RWD + 8);
                const float4 q3 = *reinterpret_cast<const float4*>(bp + c*RWD + 12);
                const float4 q4 = *reinterpret_cast<const float4*>(bp + c*RWD + 16);
                const float bv[20] = {q0.x,q0.y,q0.z,q0.w, q1.x,q1.y,q1.z,q1.w,
                                      q2.x,q2.y,q2.z,q2.w, q3.x,q3.y,q3.z,q3.w,
                                      q4.x,q4.y,q4.z,q4.w};
#pragma unroll
                for (int dj = 0; dj < 16; dj++) {
                    acc[dj][0] += a.x*bv[dj+0];
                    acc[dj][1] += a.y*bv[dj+1];
                    acc[dj][2] += a.z*bv[dj+2];
                    acc[dj][3] += a.w*bv[dj+3];
                }
            }
        }
        __syncthreads();
    }

    if (act) {
        float* op = out + ((size_t)(b*273 + 81 + dg*16)*HH + y)*WW + x0t + xg*4;
#pragma unroll
        for (int dj = 0; dj < 16; dj++) {
            float4 v;
            v.x = lrelu(acc[dj][0]);
            v.y = lrelu(acc[dj][1]);
            v.z = lrelu(acc[dj][2]);
            v.w = lrelu(acc[dj][3]);
            *reinterpret_cast<float4*>(op + (size_t)dj*HW) = v;
        }
    }
}

// ===========================================================================
// 81-channel cost volume, 8-wide x-span per thread (plain FFMA):
// thread (t<117): dy = t/13, xg = t%13; tile 9 dx x 8 x.
// LDS per c-iter: 6xLDS.128 for 72 MACs (1.33 B/MAC, crossbar unbound).
// ===========================================================================
#define TXC 104
#define CTC 8
#define BWC 112                          // 104 + 8 halo
#define NTC (CC/CTC)                     // 8 pipeline stages
#define CORR_BUF (CTC*TXC + 9*CTC*BWC)   // 8896 floats per buffer
#define CORR_SMEM (2*CORR_BUF*4)         // 71168 B

__global__ __launch_bounds__(128, 3)
void corr_kernel(const float* __restrict__ x1, float* __restrict__ out) {
    extern __shared__ float sm[];

    const int x0t = blockIdx.x * TXC;
    const int y = blockIdx.y, b = blockIdx.z;
    const int t = threadIdx.x;
    const int dy = t / 13;
    const int xg = t - dy*13;
    const bool act = (t < 117);

    const float* x1p = x1 + (size_t)b*CHW + (size_t)y*WW + x0t;
    const float* wp  = g_x2w + (size_t)b*CHW;

    float acc[9][8];
#pragma unroll
    for (int i = 0; i < 9; i++)
#pragma unroll
        for (int j = 0; j < 8; j++) acc[i][j] = 0.f;

    // hoisted load indices: s_a = 208 f4 (2 per thread), s_b = 9*224 f4
    const int ca0 = t / 13,  xa0 = (t - 13*ca0) * 8;        // covers 104 f4 x2
    const int cb  = t / 28,  xb4 = (t - 28*cb) * 4;
    const int gx2 = x0t - 4 + xb4;
    const bool px = ((unsigned)gx2 < WW);

    auto load_tile = [&](int bi, int kt) {
        float* da = sm + bi*CORR_BUF;
        float* db = da + CTC*TXC;
        const int ct = kt * CTC;
        if (t < 104) {   // 8 rows x 13 threads, 2 f4 each
            __pipeline_memcpy_async(da + ca0*TXC + xa0,
                                    x1p + (size_t)(ct+ca0)*HW + xa0, 16);
            __pipeline_memcpy_async(da + ca0*TXC + xa0 + 4,
                                    x1p + (size_t)(ct+ca0)*HW + xa0 + 4, 16);
        }
        // s_b: 8 c-rows x 28 f4 per dy-row, 9 rows; 112 threads do 9x2 each
        if (t < 112) {
            const float* srcb = wp + (size_t)(ct+cb)*HW + gx2;
            float* dstb = db + cb*BWC + xb4;
#pragma unroll
            for (int r = 0; r < 9; r++) {
                const int gy2 = y + r - 4;
                if (px && (unsigned)gy2 < HH)
                    __pipeline_memcpy_async(dstb + r*(CTC*BWC), srcb + gy2*WW, 16);
                else
                    *reinterpret_cast<float4*>(dstb + r*(CTC*BWC)) =
                        make_float4(0.f,0.f,0.f,0.f);
            }
            const float* srcb2 = srcb + 112;   // second half: threads cover cols 112..223? no:
        }
        // second pass for remaining b columns: threads 0..111 handled cols via cb/xb4
        // (full 224 f4 per dy-row needs 2 passes of 112)
        if (t < 112) {
            const int cb2 = (t + 112) / 28, xb42 = ((t + 112) - 28*cb2) * 4;
            const int gx22 = x0t - 4 + xb42;
            const bool px2 = ((unsigned)gx22 < WW);
            const float* srcb = wp + (size_t)(ct+cb2)*HW + gx22;
            float* dstb = db + cb2*BWC + xb42;
#pragma unroll
            for (int r = 0; r < 9; r++) {
                const int gy2 = y + r - 4;
                if (px2 && (unsigned)gy2 < HH)
                    __pipeline_memcpy_async(dstb + r*(CTC*BWC), srcb + gy2*WW, 16);
                else
                    *reinterpret_cast<float4*>(dstb + r*(CTC*BWC)) =
                        make_float4(0.f,0.f,0.f,0.f);
            }
        }
    };

    load_tile(0, 0);
    __pipeline_commit();

    for (int k = 0; k < NTC; k++) {
        if (k + 1 < NTC) {
            load_tile((k+1) & 1, k+1);
            __pipeline_commit();
            __pipeline_wait_prior(1);
        } else {
            __pipeline_wait_prior(0);
        }
        __syncthreads();

        if (act) {
            const float* da = sm + (k&1)*CORR_BUF;
            const float* ap = da + xg*8;
            const float* bp = da + CTC*TXC + dy*(CTC*BWC) + xg*8;
#pragma unroll
            for (int c = 0; c < CTC; c++) {
                const float4 A0 = *reinterpret_cast<const float4*>(ap + c*TXC);
                const float4 A1 = *reinterpret_cast<const float4*>(ap + c*TXC + 4);
                const float av[8] = {A0.x,A0.y,A0.z,A0.w, A1.x,A1.y,A1.z,A1.w};
                const float4 q0 = *reinterpret_cast<const float4*>(bp + c*BWC);
                const float4 q1 = *reinterpret_cast<const float4*>(bp + c*BWC + 4);
                const float4 q2 = *reinterpret_cast<const float4*>(bp + c*BWC + 8);
                const float4 q3 = *reinterpret_cast<const float4*>(bp + c*BWC + 12);
                const float bv[16] = {q0.x,q0.y,q0.z,q0.w, q1.x,q1.y,q1.z,q1.w,
                                      q2.x,q2.y,q2.z,q2.w, q3.x,q3.y,q3.z,q3.w};
#pragma unroll
                for (int dx = 0; dx < 9; dx++) {
#pragma unroll
                    for (int j = 0; j < 8; j++)
                        acc[dx][j] += av[j]*bv[dx+j];
                }
            }
        }
        __syncthreads();
    }

    if (act) {
        float* op = out + ((size_t)(b*273 + dy*9)*HH + y)*WW + x0t + xg*8;
#pragma unroll
        for (int dx = 0; dx < 9; dx++) {
            float4 v0, v1;
            v0.x = lrelu(acc[dx][0]); v0.y = lrelu(acc[dx][1]);
            v0.z = lrelu(acc[dx][2]); v0.w = lrelu(acc[dx][3]);
            v1.x = lrelu(acc[dx][4]); v1.y = lrelu(acc[dx][5]);
            v1.z = lrelu(acc[dx][6]); v1.w = lrelu(acc[dx][7]);
            *reinterpret_cast<float4*>(op + (size_t)dx*HW)     = v0;
            *reinterpret_cast<float4*>(op + (size_t)dx*HW + 4) = v1;
        }
    }
}

// ===========================================================================
extern "C" void kernel_launch(void* const* d_in, const int* in_sizes, int n_in,
                              void* d_out, int out_size) {
    const float* x1   = (const float*)d_in[0];
    const float* x2   = (const float*)d_in[1];
    const float* r1   = (const float*)d_in[2];
    const float* flow = (const float*)d_in[3];
    float* out = (float*)d_out;

    cudaFuncSetAttribute(fused_disp_warp, cudaFuncAttributeMaxDynamicSharedMemorySize, DSP_SMEM);
    cudaFuncSetAttribute(corr_kernel, cudaFuncAttributeMaxDynamicSharedMemorySize, CORR_SMEM);

    fused_disp_warp<<<dim3(8, HH, BB), 320, DSP_SMEM>>>(x1, r1, x2, flow, out);
    corr_kernel<<<dim3(WW/TXC, HH, BB), 128, CORR_SMEM>>>(x1, out);
}